// round 2
// baseline (speedup 1.0000x reference)
#include <cuda_runtime.h>

#define M_TOTAL 32768
#define DHALF   256
#define D2      512
#define KCB     4096

#define BLK_M 64
#define BLK_N 128
#define BK    16
#define NTILES (KCB / BLK_N)   // 32
#define KSTEPS (D2 / BK)       // 32

#define OUT_REAL_OFF 0
#define OUT_IMAG_OFF 8388608
#define OUT_LOSS_OFF 16777216
#define OUT_IDX_OFF  16777217

__device__ __align__(16) float g_cnorm[KCB];
__device__ int   g_prev[M_TOTAL];
__device__ int   g_idx[M_TOTAL];
__device__ float g_rowsum[M_TOTAL];

// ---------------------------------------------------------------------------
// packed f32x2 FMA (Blackwell sm_103a FFMA2) — only reachable via PTX
// ---------------------------------------------------------------------------
__device__ __forceinline__ float2 ffma2(float2 a, float2 b, float2 c) {
    union U { float2 f; unsigned long long u; };
    U A, B, C, D;
    A.f = a; B.f = b; C.f = c;
    asm("fma.rn.f32x2 %0, %1, %2, %3;" : "=l"(D.u) : "l"(A.u), "l"(B.u), "l"(C.u));
    return D.f;
}

// ---------------------------------------------------------------------------
// Kernel 0: normalize prev_symbol_idx (int64 vs int32 sniff) into g_prev
// ---------------------------------------------------------------------------
__global__ void prev_kernel(const void* __restrict__ p) {
    const long long* p64 = (const long long*)p;
    const int*       p32 = (const int*)p;
    bool is64 = true;
    for (int t = 0; t < 64; t++) {
        long long v = p64[t];
        if (v < 0 || v >= KCB) { is64 = false; break; }
    }
    int i = blockIdx.x * blockDim.x + threadIdx.x;
    if (i < M_TOTAL) g_prev[i] = is64 ? (int)p64[i] : p32[i];
}

// ---------------------------------------------------------------------------
// Kernel 1: cnorm[k] = ||codebook[k]||^2   (one warp per code)
// ---------------------------------------------------------------------------
__global__ void cnorm_kernel(const float* __restrict__ cb) {
    int warp = (blockIdx.x * blockDim.x + threadIdx.x) >> 5;
    int lane = threadIdx.x & 31;
    if (warp >= KCB) return;
    const float4* row = reinterpret_cast<const float4*>(cb + (size_t)warp * D2);
    float s = 0.f;
#pragma unroll
    for (int w = 0; w < 4; w++) {
        float4 v = row[lane + 32 * w];
        s += v.x * v.x + v.y * v.y + v.z * v.z + v.w * v.w;
    }
#pragma unroll
    for (int o = 16; o; o >>= 1) s += __shfl_xor_sync(0xffffffffu, s, o);
    if (lane == 0) g_cnorm[warp] = s;
}

// ---------------------------------------------------------------------------
// Kernel 2: fused GEMM + bias + argmin.
//   score[m][k] = ||c_k||^2 - 2*z_m.c_k - 0.8*sigmoid(adj[prev[m]][k])
//   (||z||^2 dropped: constant per row under argmin)
// BLK_M=64 rows per block, loops all K=4096 in 32 tiles of 128, BK=16.
// 256 threads as 16x16; microtile 4(m) x 8(n) with f32x2 accumulators.
// ---------------------------------------------------------------------------
__global__ __launch_bounds__(256, 2) void argmin_kernel(
    const float* __restrict__ zr, const float* __restrict__ zi,
    const float* __restrict__ cb, const float* __restrict__ adj)
{
    __shared__ __align__(16) float As[BK][BLK_M];    // [kd][m]
    __shared__ __align__(16) float Bs[BK][BLK_N];    // [kd][n]
    __shared__ int sPrev[BLK_M];
    __shared__ unsigned long long sRed[BLK_M][16];

    const int tid = threadIdx.x;
    const int tx  = tid & 15;         // n group
    const int ty  = tid >> 4;         // m group
    const int m0  = blockIdx.x * BLK_M;

    if (tid < BLK_M) sPrev[tid] = g_prev[m0 + tid];

    unsigned long long best[4] = { ~0ULL, ~0ULL, ~0ULL, ~0ULL };

    const int lm = tid >> 2;          // 0..63
    const int lk = (tid & 3) * 4;     // 0,4,8,12

    for (int nt = 0; nt < NTILES; nt++) {
        const int n0 = nt * BLK_N;

        float2 acc[4][4];
#pragma unroll
        for (int i = 0; i < 4; i++)
#pragma unroll
            for (int j = 0; j < 4; j++) acc[i][j] = make_float2(0.f, 0.f);

        for (int kt = 0; kt < KSTEPS; kt++) {
            const int kb = kt * BK;
            __syncthreads();
            // --- load A tile (z_flat slice), transposed into [kd][m] ---
            {
                int kd = kb + lk;   // whole 16-chunk lies in one half (256%16==0)
                const float* src = (kd < DHALF)
                    ? (zr + (size_t)(m0 + lm) * DHALF + kd)
                    : (zi + (size_t)(m0 + lm) * DHALF + (kd - DHALF));
                float4 v = *reinterpret_cast<const float4*>(src);
                As[lk + 0][lm] = v.x; As[lk + 1][lm] = v.y;
                As[lk + 2][lm] = v.z; As[lk + 3][lm] = v.w;
            }
            // --- load B tile (codebook slice), transposed into [kd][n] ---
#pragma unroll
            for (int r = 0; r < 2; r++) {
                int ln = lm + r * 64;
                float4 v = *reinterpret_cast<const float4*>(
                    cb + (size_t)(n0 + ln) * D2 + kb + lk);
                Bs[lk + 0][ln] = v.x; Bs[lk + 1][ln] = v.y;
                Bs[lk + 2][ln] = v.z; Bs[lk + 3][ln] = v.w;
            }
            __syncthreads();

#pragma unroll
            for (int kk = 0; kk < BK; kk++) {
                float4 a4 = *reinterpret_cast<const float4*>(&As[kk][ty * 4]);
                float4 b0 = *reinterpret_cast<const float4*>(&Bs[kk][tx * 8]);
                float4 b1 = *reinterpret_cast<const float4*>(&Bs[kk][tx * 8 + 4]);
                float2 bb[4] = { make_float2(b0.x, b0.y), make_float2(b0.z, b0.w),
                                 make_float2(b1.x, b1.y), make_float2(b1.z, b1.w) };
                float  av[4] = { a4.x, a4.y, a4.z, a4.w };
#pragma unroll
                for (int i = 0; i < 4; i++) {
                    float2 ad = make_float2(av[i], av[i]);
#pragma unroll
                    for (int j = 0; j < 4; j++)
                        acc[i][j] = ffma2(ad, bb[j], acc[i][j]);
                }
            }
        }

        // --- epilogue: bias + score + running argmin ---
        float4 cn0 = *reinterpret_cast<const float4*>(&g_cnorm[n0 + tx * 8]);
        float4 cn1 = *reinterpret_cast<const float4*>(&g_cnorm[n0 + tx * 8 + 4]);
        float cn[8] = { cn0.x, cn0.y, cn0.z, cn0.w, cn1.x, cn1.y, cn1.z, cn1.w };

#pragma unroll
        for (int i = 0; i < 4; i++) {
            const float* arow = adj + (size_t)sPrev[ty * 4 + i] * KCB + n0 + tx * 8;
            float4 g0 = *reinterpret_cast<const float4*>(arow);
            float4 g1 = *reinterpret_cast<const float4*>(arow + 4);
            float gv[8]  = { g0.x, g0.y, g0.z, g0.w, g1.x, g1.y, g1.z, g1.w };
            float dv[8]  = { acc[i][0].x, acc[i][0].y, acc[i][1].x, acc[i][1].y,
                             acc[i][2].x, acc[i][2].y, acc[i][3].x, acc[i][3].y };
#pragma unroll
            for (int j = 0; j < 8; j++) {
                float x  = gv[j];
                float x2 = x * x;
                // 0.8*sigmoid(x) = 0.4 + 0.8*x*p(x^2), odd Taylor to x^9
                float p = 2.1356922e-05f;
                p = fmaf(p, x2, -2.1081349e-04f);
                p = fmaf(p, x2,  2.0833334e-03f);
                p = fmaf(p, x2, -2.0833333e-02f);
                p = fmaf(p, x2,  0.25f);
                float sig08 = fmaf(0.8f * x, p, 0.4f);
                if (fabsf(x) > 1.0f)                    // never hit for this data
                    sig08 = 0.8f / (1.0f + __expf(-x));
                float score = cn[j] - 2.0f * dv[j] - sig08;
                unsigned u = __float_as_uint(score);
                u = (u & 0x80000000u) ? ~u : (u | 0x80000000u);   // order-preserving
                unsigned long long cand =
                    ((unsigned long long)u << 32) | (unsigned)(n0 + tx * 8 + j);
                best[i] = (cand < best[i]) ? cand : best[i];
            }
        }
    }

    __syncthreads();
#pragma unroll
    for (int i = 0; i < 4; i++) sRed[ty * 4 + i][tx] = best[i];
    __syncthreads();
    if (tid < BLK_M) {
        unsigned long long b = sRed[tid][0];
#pragma unroll
        for (int t = 1; t < 16; t++) {
            unsigned long long c = sRed[tid][t];
            b = (c < b) ? c : b;
        }
        g_idx[m0 + tid] = (int)(b & 0xffffffffu);
    }
}

// ---------------------------------------------------------------------------
// Kernel 3: gather z_q = codebook[idx], write outputs, per-row squared error
// ---------------------------------------------------------------------------
__global__ void gather_kernel(const float* __restrict__ zr,
                              const float* __restrict__ zi,
                              const float* __restrict__ cb,
                              float* __restrict__ out)
{
    __shared__ float sw[4];
    const int row = blockIdx.x;
    const int tid = threadIdx.x;   // 128 threads, 4 floats each
    const int idx = g_idx[row];
    const int j   = tid * 4;

    float4 c = *reinterpret_cast<const float4*>(cb + (size_t)idx * D2 + j);
    float4 z;
    float* o;
    if (j < DHALF) {
        z = *reinterpret_cast<const float4*>(zr + (size_t)row * DHALF + j);
        o = out + OUT_REAL_OFF + (size_t)row * DHALF + j;
    } else {
        z = *reinterpret_cast<const float4*>(zi + (size_t)row * DHALF + (j - DHALF));
        o = out + OUT_IMAG_OFF + (size_t)row * DHALF + (j - DHALF);
    }
    *reinterpret_cast<float4*>(o) = c;

    float dx = c.x - z.x, dy = c.y - z.y, dz = c.z - z.z, dw = c.w - z.w;
    float s = dx * dx + dy * dy + dz * dz + dw * dw;
#pragma unroll
    for (int of = 16; of; of >>= 1) s += __shfl_xor_sync(0xffffffffu, s, of);
    if ((tid & 31) == 0) sw[tid >> 5] = s;
    __syncthreads();
    if (tid == 0) {
        g_rowsum[row] = sw[0] + sw[1] + sw[2] + sw[3];
        out[OUT_IDX_OFF + row] = (float)idx;
    }
}

// ---------------------------------------------------------------------------
// Kernel 4: deterministic final loss reduction
// ---------------------------------------------------------------------------
__global__ void loss_kernel(float* __restrict__ out) {
    __shared__ float sm[1024];
    const int tid = threadIdx.x;
    float s = 0.f;
#pragma unroll 1
    for (int k = 0; k < 32; k++) s += g_rowsum[tid + 1024 * k];
    sm[tid] = s;
    __syncthreads();
    for (int off = 512; off; off >>= 1) {
        if (tid < off) sm[tid] += sm[tid + off];
        __syncthreads();
    }
    if (tid == 0) out[OUT_LOSS_OFF] = sm[0] * (1.01f / 16777216.0f);
}

// ---------------------------------------------------------------------------
extern "C" void kernel_launch(void* const* d_in, const int* in_sizes, int n_in,
                              void* d_out, int out_size) {
    const float* zr   = (const float*)d_in[0];
    const float* zi   = (const float*)d_in[1];
    const void*  prev = d_in[2];
    const float* cb   = (const float*)d_in[3];
    const float* adj  = (const float*)d_in[4];
    float* out = (float*)d_out;

    prev_kernel<<<(M_TOTAL + 255) / 256, 256>>>(prev);
    cnorm_kernel<<<KCB / 8, 256>>>(cb);
    argmin_kernel<<<M_TOTAL / BLK_M, 256>>>(zr, zi, cb, adj);
    gather_kernel<<<M_TOTAL, 128>>>(zr, zi, cb, out);
    loss_kernel<<<1, 1024>>>(out);
}

// round 3
// speedup vs baseline: 1.0418x; 1.0418x over previous
#include <cuda_runtime.h>

#define M_TOTAL 32768
#define DHALF   256
#define D2      512
#define KCB     4096

#define BLK_M 64
#define BLK_N 128
#define BK    16
#define NTILES (KCB / BLK_N)   // 32
#define KSTEPS (D2 / BK)       // 32

#define OUT_REAL_OFF 0
#define OUT_IMAG_OFF 8388608
#define OUT_LOSS_OFF 16777216
#define OUT_IDX_OFF  16777217

__device__ __align__(16) float g_cnorm[KCB];
__device__ int   g_prev[M_TOTAL];
__device__ int   g_idx[M_TOTAL];
__device__ float g_rowsum[M_TOTAL];

// ---------------------------------------------------------------------------
// packed f32x2 FMA (Blackwell sm_103a FFMA2) — only reachable via PTX
// ---------------------------------------------------------------------------
__device__ __forceinline__ float2 ffma2(float2 a, float2 b, float2 c) {
    union U { float2 f; unsigned long long u; };
    U A, B, C, D;
    A.f = a; B.f = b; C.f = c;
    asm("fma.rn.f32x2 %0, %1, %2, %3;" : "=l"(D.u) : "l"(A.u), "l"(B.u), "l"(C.u));
    return D.f;
}

// ---------------------------------------------------------------------------
// Kernel 0: normalize prev_symbol_idx (int64 vs int32 sniff) into g_prev
// ---------------------------------------------------------------------------
__global__ void prev_kernel(const void* __restrict__ p) {
    const long long* p64 = (const long long*)p;
    const int*       p32 = (const int*)p;
    bool is64 = true;
    for (int t = 0; t < 64; t++) {
        long long v = p64[t];
        if (v < 0 || v >= KCB) { is64 = false; break; }
    }
    int i = blockIdx.x * blockDim.x + threadIdx.x;
    if (i < M_TOTAL) g_prev[i] = is64 ? (int)p64[i] : p32[i];
}

// ---------------------------------------------------------------------------
// Kernel 1: cnorm[k] = ||codebook[k]||^2   (one warp per code)
// ---------------------------------------------------------------------------
__global__ void cnorm_kernel(const float* __restrict__ cb) {
    int warp = (blockIdx.x * blockDim.x + threadIdx.x) >> 5;
    int lane = threadIdx.x & 31;
    if (warp >= KCB) return;
    const float4* row = reinterpret_cast<const float4*>(cb + (size_t)warp * D2);
    float s = 0.f;
#pragma unroll
    for (int w = 0; w < 4; w++) {
        float4 v = row[lane + 32 * w];
        s += v.x * v.x + v.y * v.y + v.z * v.z + v.w * v.w;
    }
#pragma unroll
    for (int o = 16; o; o >>= 1) s += __shfl_xor_sync(0xffffffffu, s, o);
    if (lane == 0) g_cnorm[warp] = s;
}

// ---------------------------------------------------------------------------
// Kernel 2: fused GEMM + bias + argmin, register-staged double buffering.
//   score[m][k] = ||c_k||^2 - 2*z_m.c_k - 0.8*sigmoid(adj[prev[m]][k])
// BLK_M=64 rows/block, 32 N-tiles of 128, BK=16, 2 smem stages,
// one __syncthreads per k-step; LDG(kt+1) overlapped with compute(kt).
// ---------------------------------------------------------------------------
__global__ __launch_bounds__(256, 2) void argmin_kernel(
    const float* __restrict__ zr, const float* __restrict__ zi,
    const float* __restrict__ cb, const float* __restrict__ adj)
{
    __shared__ __align__(16) float As[2][BK][BLK_M];    // [stage][kd][m]
    __shared__ __align__(16) float Bs[2][BK][BLK_N];    // [stage][kd][n]
    __shared__ int sPrev[BLK_M];
    __shared__ unsigned long long sRed[BLK_M][16];

    const int tid = threadIdx.x;
    const int tx  = tid & 15;         // n group
    const int ty  = tid >> 4;         // m group
    const int m0  = blockIdx.x * BLK_M;

    if (tid < BLK_M) sPrev[tid] = g_prev[m0 + tid];

    unsigned long long best[4] = { ~0ULL, ~0ULL, ~0ULL, ~0ULL };

    const int lm = tid >> 2;          // 0..63
    const int lk = (tid & 3) * 4;     // 0,4,8,12

    // per-thread A source base (row m0+lm); 16-col chunks never straddle halves
    const float* const arow_r = zr + (size_t)(m0 + lm) * DHALF;
    const float* const arow_i = zi + (size_t)(m0 + lm) * DHALF;

    for (int nt = 0; nt < NTILES; nt++) {
        const int n0 = nt * BLK_N;
        const float* const brow0 = cb + (size_t)(n0 + lm)      * D2 + lk;
        const float* const brow1 = cb + (size_t)(n0 + lm + 64) * D2 + lk;

        float2 acc[4][4];
#pragma unroll
        for (int i = 0; i < 4; i++)
#pragma unroll
            for (int j = 0; j < 4; j++) acc[i][j] = make_float2(0.f, 0.f);

        // ---- preload k-tile 0 into stage 0 ----
        {
            int kd = lk;  // kt=0
            float4 va = *reinterpret_cast<const float4*>(
                (kd < DHALF) ? (arow_r + kd) : (arow_i + kd - DHALF));
            float4 vb0 = *reinterpret_cast<const float4*>(brow0);
            float4 vb1 = *reinterpret_cast<const float4*>(brow1);
            As[0][lk + 0][lm] = va.x;  As[0][lk + 1][lm] = va.y;
            As[0][lk + 2][lm] = va.z;  As[0][lk + 3][lm] = va.w;
            Bs[0][lk + 0][lm] = vb0.x; Bs[0][lk + 1][lm] = vb0.y;
            Bs[0][lk + 2][lm] = vb0.z; Bs[0][lk + 3][lm] = vb0.w;
            Bs[0][lk + 0][lm + 64] = vb1.x; Bs[0][lk + 1][lm + 64] = vb1.y;
            Bs[0][lk + 2][lm + 64] = vb1.z; Bs[0][lk + 3][lm + 64] = vb1.w;
        }

        for (int kt = 0; kt < KSTEPS; kt++) {
            __syncthreads();   // stage (kt&1) ready; stage ((kt+1)&1) free to write

            // ---- issue next tile's global loads (latency hidden by compute) ----
            float4 na, nb0, nb1;
            const int nk = kt + 1;
            if (nk < KSTEPS) {
                int kd = nk * BK + lk;
                na  = *reinterpret_cast<const float4*>(
                    (kd < DHALF) ? (arow_r + kd) : (arow_i + kd - DHALF));
                nb0 = *reinterpret_cast<const float4*>(brow0 + nk * BK);
                nb1 = *reinterpret_cast<const float4*>(brow1 + nk * BK);
            }

            // ---- compute on current stage ----
            const int cur = kt & 1;
#pragma unroll
            for (int kk = 0; kk < BK; kk++) {
                float4 a4 = *reinterpret_cast<const float4*>(&As[cur][kk][ty * 4]);
                float4 b0 = *reinterpret_cast<const float4*>(&Bs[cur][kk][tx * 8]);
                float4 b1 = *reinterpret_cast<const float4*>(&Bs[cur][kk][tx * 8 + 4]);
                float2 bb[4] = { make_float2(b0.x, b0.y), make_float2(b0.z, b0.w),
                                 make_float2(b1.x, b1.y), make_float2(b1.z, b1.w) };
                float  av[4] = { a4.x, a4.y, a4.z, a4.w };
#pragma unroll
                for (int i = 0; i < 4; i++) {
                    float2 ad = make_float2(av[i], av[i]);
#pragma unroll
                    for (int j = 0; j < 4; j++)
                        acc[i][j] = ffma2(ad, bb[j], acc[i][j]);
                }
            }

            // ---- stage next tile ----
            if (nk < KSTEPS) {
                const int nxt = nk & 1;
                As[nxt][lk + 0][lm] = na.x;  As[nxt][lk + 1][lm] = na.y;
                As[nxt][lk + 2][lm] = na.z;  As[nxt][lk + 3][lm] = na.w;
                Bs[nxt][lk + 0][lm] = nb0.x; Bs[nxt][lk + 1][lm] = nb0.y;
                Bs[nxt][lk + 2][lm] = nb0.z; Bs[nxt][lk + 3][lm] = nb0.w;
                Bs[nxt][lk + 0][lm + 64] = nb1.x; Bs[nxt][lk + 1][lm + 64] = nb1.y;
                Bs[nxt][lk + 2][lm + 64] = nb1.z; Bs[nxt][lk + 3][lm + 64] = nb1.w;
            }
        }

        // --- epilogue: bias + score + running argmin ---
        float4 cn0 = *reinterpret_cast<const float4*>(&g_cnorm[n0 + tx * 8]);
        float4 cn1 = *reinterpret_cast<const float4*>(&g_cnorm[n0 + tx * 8 + 4]);
        float cn[8] = { cn0.x, cn0.y, cn0.z, cn0.w, cn1.x, cn1.y, cn1.z, cn1.w };

#pragma unroll
        for (int i = 0; i < 4; i++) {
            const float* arow = adj + (size_t)sPrev[ty * 4 + i] * KCB + n0 + tx * 8;
            float4 g0 = *reinterpret_cast<const float4*>(arow);
            float4 g1 = *reinterpret_cast<const float4*>(arow + 4);
            float gv[8]  = { g0.x, g0.y, g0.z, g0.w, g1.x, g1.y, g1.z, g1.w };
            float dv[8]  = { acc[i][0].x, acc[i][0].y, acc[i][1].x, acc[i][1].y,
                             acc[i][2].x, acc[i][2].y, acc[i][3].x, acc[i][3].y };
#pragma unroll
            for (int j = 0; j < 8; j++) {
                float x  = gv[j];
                float x2 = x * x;
                // 0.8*sigmoid(x) = 0.4 + 0.8*x*p(x^2), odd Taylor to x^9
                float p = 2.1356922e-05f;
                p = fmaf(p, x2, -2.1081349e-04f);
                p = fmaf(p, x2,  2.0833334e-03f);
                p = fmaf(p, x2, -2.0833333e-02f);
                p = fmaf(p, x2,  0.25f);
                float sig08 = fmaf(0.8f * x, p, 0.4f);
                if (fabsf(x) > 1.0f)                    // never hit for this data
                    sig08 = 0.8f / (1.0f + __expf(-x));
                float score = cn[j] - 2.0f * dv[j] - sig08;
                unsigned u = __float_as_uint(score);
                u = (u & 0x80000000u) ? ~u : (u | 0x80000000u);   // order-preserving
                unsigned long long cand =
                    ((unsigned long long)u << 32) | (unsigned)(n0 + tx * 8 + j);
                best[i] = (cand < best[i]) ? cand : best[i];
            }
        }
        __syncthreads();   // protect stage reuse across nt iterations
    }

#pragma unroll
    for (int i = 0; i < 4; i++) sRed[ty * 4 + i][tx] = best[i];
    __syncthreads();
    if (tid < BLK_M) {
        unsigned long long b = sRed[tid][0];
#pragma unroll
        for (int t = 1; t < 16; t++) {
            unsigned long long c = sRed[tid][t];
            b = (c < b) ? c : b;
        }
        g_idx[m0 + tid] = (int)(b & 0xffffffffu);
    }
}

// ---------------------------------------------------------------------------
// Kernel 3: gather z_q = codebook[idx], write outputs, per-row squared error
// ---------------------------------------------------------------------------
__global__ void gather_kernel(const float* __restrict__ zr,
                              const float* __restrict__ zi,
                              const float* __restrict__ cb,
                              float* __restrict__ out)
{
    __shared__ float sw[4];
    const int row = blockIdx.x;
    const int tid = threadIdx.x;   // 128 threads, 4 floats each
    const int idx = g_idx[row];
    const int j   = tid * 4;

    float4 c = *reinterpret_cast<const float4*>(cb + (size_t)idx * D2 + j);
    float4 z;
    float* o;
    if (j < DHALF) {
        z = *reinterpret_cast<const float4*>(zr + (size_t)row * DHALF + j);
        o = out + OUT_REAL_OFF + (size_t)row * DHALF + j;
    } else {
        z = *reinterpret_cast<const float4*>(zi + (size_t)row * DHALF + (j - DHALF));
        o = out + OUT_IMAG_OFF + (size_t)row * DHALF + (j - DHALF);
    }
    *reinterpret_cast<float4*>(o) = c;

    float dx = c.x - z.x, dy = c.y - z.y, dz = c.z - z.z, dw = c.w - z.w;
    float s = dx * dx + dy * dy + dz * dz + dw * dw;
#pragma unroll
    for (int of = 16; of; of >>= 1) s += __shfl_xor_sync(0xffffffffu, s, of);
    if ((tid & 31) == 0) sw[tid >> 5] = s;
    __syncthreads();
    if (tid == 0) {
        g_rowsum[row] = sw[0] + sw[1] + sw[2] + sw[3];
        out[OUT_IDX_OFF + row] = (float)idx;
    }
}

// ---------------------------------------------------------------------------
// Kernel 4: deterministic final loss reduction
// ---------------------------------------------------------------------------
__global__ void loss_kernel(float* __restrict__ out) {
    __shared__ float sm[1024];
    const int tid = threadIdx.x;
    float s = 0.f;
#pragma unroll 1
    for (int k = 0; k < 32; k++) s += g_rowsum[tid + 1024 * k];
    sm[tid] = s;
    __syncthreads();
    for (int off = 512; off; off >>= 1) {
        if (tid < off) sm[tid] += sm[tid + off];
        __syncthreads();
    }
    if (tid == 0) out[OUT_LOSS_OFF] = sm[0] * (1.01f / 16777216.0f);
}

// ---------------------------------------------------------------------------
extern "C" void kernel_launch(void* const* d_in, const int* in_sizes, int n_in,
                              void* d_out, int out_size) {
    const float* zr   = (const float*)d_in[0];
    const float* zi   = (const float*)d_in[1];
    const void*  prev = d_in[2];
    const float* cb   = (const float*)d_in[3];
    const float* adj  = (const float*)d_in[4];
    float* out = (float*)d_out;

    prev_kernel<<<(M_TOTAL + 255) / 256, 256>>>(prev);
    cnorm_kernel<<<KCB / 8, 256>>>(cb);
    argmin_kernel<<<M_TOTAL / BLK_M, 256>>>(zr, zi, cb, adj);
    gather_kernel<<<M_TOTAL, 128>>>(zr, zi, cb, out);
    loss_kernel<<<1, 1024>>>(out);
}

// round 4
// speedup vs baseline: 1.5871x; 1.5234x over previous
#include <cuda_runtime.h>

#define M_TOTAL 32768
#define DHALF   256
#define D2      512
#define KCB     4096

#define BLK_M 128
#define BLK_N 128
#define BK    16
#define NTILES (KCB / BLK_N)   // 32
#define KSTEPS (D2 / BK)       // 32

#define OUT_REAL_OFF 0
#define OUT_IMAG_OFF 8388608
#define OUT_LOSS_OFF 16777216
#define OUT_IDX_OFF  16777217

__device__ __align__(16) float g_cnorm[KCB];
__device__ int   g_prev[M_TOTAL];
__device__ int   g_idx[M_TOTAL];
__device__ float g_rowsum[M_TOTAL];

// ---------------------------------------------------------------------------
// packed f32x2 FMA (Blackwell sm_103a FFMA2) — only reachable via PTX
// ---------------------------------------------------------------------------
__device__ __forceinline__ float2 ffma2(float2 a, float2 b, float2 c) {
    union U { float2 f; unsigned long long u; };
    U A, B, C, D;
    A.f = a; B.f = b; C.f = c;
    asm("fma.rn.f32x2 %0, %1, %2, %3;" : "=l"(D.u) : "l"(A.u), "l"(B.u), "l"(C.u));
    return D.f;
}

// ---------------------------------------------------------------------------
// Kernel 0: normalize prev_symbol_idx (int64 vs int32 sniff) into g_prev
// ---------------------------------------------------------------------------
__global__ void prev_kernel(const void* __restrict__ p) {
    const long long* p64 = (const long long*)p;
    const int*       p32 = (const int*)p;
    bool is64 = true;
    for (int t = 0; t < 64; t++) {
        long long v = p64[t];
        if (v < 0 || v >= KCB) { is64 = false; break; }
    }
    int i = blockIdx.x * blockDim.x + threadIdx.x;
    if (i < M_TOTAL) g_prev[i] = is64 ? (int)p64[i] : p32[i];
}

// ---------------------------------------------------------------------------
// Kernel 1: cnorm[k] = ||codebook[k]||^2   (one warp per code)
// ---------------------------------------------------------------------------
__global__ void cnorm_kernel(const float* __restrict__ cb) {
    int warp = (blockIdx.x * blockDim.x + threadIdx.x) >> 5;
    int lane = threadIdx.x & 31;
    if (warp >= KCB) return;
    const float4* row = reinterpret_cast<const float4*>(cb + (size_t)warp * D2);
    float s = 0.f;
#pragma unroll
    for (int w = 0; w < 4; w++) {
        float4 v = row[lane + 32 * w];
        s += v.x * v.x + v.y * v.y + v.z * v.z + v.w * v.w;
    }
#pragma unroll
    for (int o = 16; o; o >>= 1) s += __shfl_xor_sync(0xffffffffu, s, o);
    if (lane == 0) g_cnorm[warp] = s;
}

// ---------------------------------------------------------------------------
// Kernel 2: fused GEMM + bias + argmin.
//   score[m][k] = ||c_k||^2 - 2*z_m.c_k - 0.8*sigmoid(adj[prev[m]][k])
// 128x128 block tile, 8x8 microtile per thread (256 threads, 16x16),
// BK=16, double-buffered smem, one __syncthreads per k-step.
// Per kk: 4 LDS.128 for 32 FFMA2 -> LDS and fma pipes balanced.
// ---------------------------------------------------------------------------
__global__ __launch_bounds__(256, 2) void argmin_kernel(
    const float* __restrict__ zr, const float* __restrict__ zi,
    const float* __restrict__ cb, const float* __restrict__ adj)
{
    __shared__ __align__(16) float As[2][BK][BLK_M];    // [stage][kd][m]
    __shared__ __align__(16) float Bs[2][BK][BLK_N];    // [stage][kd][n]
    __shared__ int sPrev[BLK_M];
    __shared__ unsigned long long sRed[BLK_M][16];      // [m][tx] argmin keys

    const int tid = threadIdx.x;
    const int tx  = tid & 15;         // n group: cols tx*4..+3 and +64
    const int ty  = tid >> 4;         // m group: rows ty*4..+3 and +64
    const int m0  = blockIdx.x * BLK_M;

    if (tid < BLK_M) sPrev[tid] = g_prev[m0 + tid];
#pragma unroll
    for (int i = 0; i < 8; i++)
        ((unsigned long long*)sRed)[tid + 256 * i] = ~0ULL;

    // ---- global-load assignment: row r = tid&127, float4-chunks c and c+2 ----
    const int r  = tid & 127;
    const int c0 = tid >> 7;          // 0 or 1; chunks c0 and c0+2 (of 4)
    const float* const arow_r = zr + (size_t)(m0 + r) * DHALF;
    const float* const arow_i = zi + (size_t)(m0 + r) * DHALF;

    for (int nt = 0; nt < NTILES; nt++) {
        const int n0 = nt * BLK_N;
        const float* const brow = cb + (size_t)(n0 + r) * D2;

        float2 acc[8][4];
#pragma unroll
        for (int i = 0; i < 8; i++)
#pragma unroll
            for (int j = 0; j < 4; j++) acc[i][j] = make_float2(0.f, 0.f);

        // ---- preload k-tile 0 into stage 0 ----
#pragma unroll
        for (int q = 0; q < 2; q++) {
            const int ch = c0 + q * 2;
            const int kd = ch * 4;    // kb = 0
            float4 va = *reinterpret_cast<const float4*>(
                (kd < DHALF) ? (arow_r + kd) : (arow_i + kd - DHALF));
            float4 vb = *reinterpret_cast<const float4*>(brow + kd);
            As[0][kd + 0][r] = va.x; As[0][kd + 1][r] = va.y;
            As[0][kd + 2][r] = va.z; As[0][kd + 3][r] = va.w;
            Bs[0][kd + 0][r] = vb.x; Bs[0][kd + 1][r] = vb.y;
            Bs[0][kd + 2][r] = vb.z; Bs[0][kd + 3][r] = vb.w;
        }

        for (int kt = 0; kt < KSTEPS; kt++) {
            __syncthreads();   // stage (kt&1) ready; other stage free

            // ---- issue next tile's global loads ----
            float4 na0, na1, nb0, nb1;
            const int nk = kt + 1;
            if (nk < KSTEPS) {
                const int kb = nk * BK;
#pragma unroll
                for (int q = 0; q < 2; q++) {
                    const int kd = kb + (c0 + q * 2) * 4;
                    float4 va = *reinterpret_cast<const float4*>(
                        (kd < DHALF) ? (arow_r + kd) : (arow_i + kd - DHALF));
                    float4 vb = *reinterpret_cast<const float4*>(brow + kd);
                    if (q == 0) { na0 = va; nb0 = vb; }
                    else        { na1 = va; nb1 = vb; }
                }
            }

            // ---- compute on current stage ----
            const int cur = kt & 1;
#pragma unroll
            for (int kk = 0; kk < BK; kk++) {
                float4 a0 = *reinterpret_cast<const float4*>(&As[cur][kk][ty * 4]);
                float4 a1 = *reinterpret_cast<const float4*>(&As[cur][kk][ty * 4 + 64]);
                float4 b0 = *reinterpret_cast<const float4*>(&Bs[cur][kk][tx * 4]);
                float4 b1 = *reinterpret_cast<const float4*>(&Bs[cur][kk][tx * 4 + 64]);
                float2 bb[4] = { make_float2(b0.x, b0.y), make_float2(b0.z, b0.w),
                                 make_float2(b1.x, b1.y), make_float2(b1.z, b1.w) };
                float  av[8] = { a0.x, a0.y, a0.z, a0.w, a1.x, a1.y, a1.z, a1.w };
#pragma unroll
                for (int i = 0; i < 8; i++) {
                    float2 ad = make_float2(av[i], av[i]);
#pragma unroll
                    for (int j = 0; j < 4; j++)
                        acc[i][j] = ffma2(ad, bb[j], acc[i][j]);
                }
            }

            // ---- stage next tile ----
            if (nk < KSTEPS) {
                const int nxt = nk & 1;
                const int kd0 = c0 * 4, kd1 = (c0 + 2) * 4;
                As[nxt][kd0 + 0][r] = na0.x; As[nxt][kd0 + 1][r] = na0.y;
                As[nxt][kd0 + 2][r] = na0.z; As[nxt][kd0 + 3][r] = na0.w;
                As[nxt][kd1 + 0][r] = na1.x; As[nxt][kd1 + 1][r] = na1.y;
                As[nxt][kd1 + 2][r] = na1.z; As[nxt][kd1 + 3][r] = na1.w;
                Bs[nxt][kd0 + 0][r] = nb0.x; Bs[nxt][kd0 + 1][r] = nb0.y;
                Bs[nxt][kd0 + 2][r] = nb0.z; Bs[nxt][kd0 + 3][r] = nb0.w;
                Bs[nxt][kd1 + 0][r] = nb1.x; Bs[nxt][kd1 + 1][r] = nb1.y;
                Bs[nxt][kd1 + 2][r] = nb1.z; Bs[nxt][kd1 + 3][r] = nb1.w;
            }
        }

        // --- epilogue: bias + score + running argmin (smem keys, owner-only) ---
        float4 cn0 = *reinterpret_cast<const float4*>(&g_cnorm[n0 + tx * 4]);
        float4 cn1 = *reinterpret_cast<const float4*>(&g_cnorm[n0 + tx * 4 + 64]);
        float cn[8] = { cn0.x, cn0.y, cn0.z, cn0.w, cn1.x, cn1.y, cn1.z, cn1.w };

#pragma unroll
        for (int i = 0; i < 8; i++) {
            const int mloc = ty * 4 + (i & 3) + (i >> 2) * 64;
            const float* arow = adj + (size_t)sPrev[mloc] * KCB + n0 + tx * 4;
            float4 g0 = *reinterpret_cast<const float4*>(arow);
            float4 g1 = *reinterpret_cast<const float4*>(arow + 64);
            float gv[8] = { g0.x, g0.y, g0.z, g0.w, g1.x, g1.y, g1.z, g1.w };
            const float* dv = reinterpret_cast<const float*>(&acc[i][0]);

            unsigned long long b = sRed[mloc][tx];
#pragma unroll
            for (int j = 0; j < 8; j++) {
                float x  = gv[j];
                float x2 = x * x;
                // 0.8*sigmoid(x) = 0.4 + 0.8*x*p(x^2), odd Taylor to x^9
                float p = 2.1356922e-05f;
                p = fmaf(p, x2, -2.1081349e-04f);
                p = fmaf(p, x2,  2.0833334e-03f);
                p = fmaf(p, x2, -2.0833333e-02f);
                p = fmaf(p, x2,  0.25f);
                float sig08 = fmaf(0.8f * x, p, 0.4f);
                if (fabsf(x) > 1.0f)                    // never hit for this data
                    sig08 = 0.8f / (1.0f + __expf(-x));
                float score = cn[j] - 2.0f * dv[j] - sig08;
                unsigned u = __float_as_uint(score);
                u = (u & 0x80000000u) ? ~u : (u | 0x80000000u);   // order-preserving
                const int n = n0 + tx * 4 + (j & 3) + (j >> 2) * 64;
                unsigned long long cand = ((unsigned long long)u << 32) | (unsigned)n;
                b = (cand < b) ? cand : b;
            }
            sRed[mloc][tx] = b;
        }
        // no sync needed: next preload writes stage 0, last read before the
        // kt=KSTEPS-1 barrier; sRed slots are single-owner.
    }

    __syncthreads();
    if (tid < BLK_M) {
        unsigned long long b = sRed[tid][0];
#pragma unroll
        for (int t = 1; t < 16; t++) {
            unsigned long long c = sRed[tid][t];
            b = (c < b) ? c : b;
        }
        g_idx[m0 + tid] = (int)(b & 0xffffffffu);
    }
}

// ---------------------------------------------------------------------------
// Kernel 3: gather z_q = codebook[idx], write outputs, per-row squared error
// ---------------------------------------------------------------------------
__global__ void gather_kernel(const float* __restrict__ zr,
                              const float* __restrict__ zi,
                              const float* __restrict__ cb,
                              float* __restrict__ out)
{
    __shared__ float sw[4];
    const int row = blockIdx.x;
    const int tid = threadIdx.x;   // 128 threads, 4 floats each
    const int idx = g_idx[row];
    const int j   = tid * 4;

    float4 c = *reinterpret_cast<const float4*>(cb + (size_t)idx * D2 + j);
    float4 z;
    float* o;
    if (j < DHALF) {
        z = *reinterpret_cast<const float4*>(zr + (size_t)row * DHALF + j);
        o = out + OUT_REAL_OFF + (size_t)row * DHALF + j;
    } else {
        z = *reinterpret_cast<const float4*>(zi + (size_t)row * DHALF + (j - DHALF));
        o = out + OUT_IMAG_OFF + (size_t)row * DHALF + (j - DHALF);
    }
    *reinterpret_cast<float4*>(o) = c;

    float dx = c.x - z.x, dy = c.y - z.y, dz = c.z - z.z, dw = c.w - z.w;
    float s = dx * dx + dy * dy + dz * dz + dw * dw;
#pragma unroll
    for (int of = 16; of; of >>= 1) s += __shfl_xor_sync(0xffffffffu, s, of);
    if ((tid & 31) == 0) sw[tid >> 5] = s;
    __syncthreads();
    if (tid == 0) {
        g_rowsum[row] = sw[0] + sw[1] + sw[2] + sw[3];
        out[OUT_IDX_OFF + row] = (float)idx;
    }
}

// ---------------------------------------------------------------------------
// Kernel 4: deterministic final loss reduction
// ---------------------------------------------------------------------------
__global__ void loss_kernel(float* __restrict__ out) {
    __shared__ float sm[1024];
    const int tid = threadIdx.x;
    float s = 0.f;
#pragma unroll 1
    for (int k = 0; k < 32; k++) s += g_rowsum[tid + 1024 * k];
    sm[tid] = s;
    __syncthreads();
    for (int off = 512; off; off >>= 1) {
        if (tid < off) sm[tid] += sm[tid + off];
        __syncthreads();
    }
    if (tid == 0) out[OUT_LOSS_OFF] = sm[0] * (1.01f / 16777216.0f);
}

// ---------------------------------------------------------------------------
extern "C" void kernel_launch(void* const* d_in, const int* in_sizes, int n_in,
                              void* d_out, int out_size) {
    const float* zr   = (const float*)d_in[0];
    const float* zi   = (const float*)d_in[1];
    const void*  prev = d_in[2];
    const float* cb   = (const float*)d_in[3];
    const float* adj  = (const float*)d_in[4];
    float* out = (float*)d_out;

    prev_kernel<<<(M_TOTAL + 255) / 256, 256>>>(prev);
    cnorm_kernel<<<KCB / 8, 256>>>(cb);
    argmin_kernel<<<M_TOTAL / BLK_M, 256>>>(zr, zi, cb, adj);
    gather_kernel<<<M_TOTAL, 128>>>(zr, zi, cb, out);
    loss_kernel<<<1, 1024>>>(out);
}

// round 6
// speedup vs baseline: 1.9955x; 1.2573x over previous
#include <cuda_runtime.h>
#include <cuda_bf16.h>
#include <cstdint>

#define M_TOTAL 32768
#define DHALF   256
#define D2      512
#define KCB     4096

#define BLK_M 128
#define BLK_N 128
#define NTILES  (KCB / BLK_N)   // 32
#define KSTAGES (D2 / 16)       // 32 k16-stages per n-tile
#define NSTAGES (NTILES * KSTAGES)  // 1024

// smem layout: per split tile 128 rows x 48B (16 bf16 data + 8 pad) = 6144B
#define SPLIT_BYTES 6144
#define STAGE_BYTES (6 * SPLIT_BYTES)          // A0,A1,A2,B0,B1,B2 = 36864
#define SRED_OFF    (2 * STAGE_BYTES)          // 73728
#define SMEM_TOTAL  (SRED_OFF + BLK_M * 16 * 8) // + 16KB keys = 90112

#define OUT_REAL_OFF 0
#define OUT_IMAG_OFF 8388608
#define OUT_LOSS_OFF 16777216
#define OUT_IDX_OFF  16777217

__device__ __align__(16) float g_cnorm[KCB];
__device__ int   g_prev[M_TOTAL];
__device__ int   g_idx[M_TOTAL];
__device__ float g_rowsum[M_TOTAL];

// ---------------------------------------------------------------------------
__device__ __forceinline__ void mma_bf16(float* d, const uint32_t* a,
                                         const uint32_t* b) {
    asm volatile(
        "mma.sync.aligned.m16n8k16.row.col.f32.bf16.bf16.f32 "
        "{%0,%1,%2,%3},{%4,%5,%6,%7},{%8,%9},{%0,%1,%2,%3};"
        : "+f"(d[0]), "+f"(d[1]), "+f"(d[2]), "+f"(d[3])
        : "r"(a[0]), "r"(a[1]), "r"(a[2]), "r"(a[3]), "r"(b[0]), "r"(b[1]));
}

// exact 3-way bf16 split: v = s0 + s1 + s2 (to 2^-27 rel)
__device__ __forceinline__ void split3(float v, unsigned short& s0,
                                       unsigned short& s1, unsigned short& s2) {
    __nv_bfloat16 b0 = __float2bfloat16(v);
    float r  = v - __bfloat162float(b0);
    __nv_bfloat16 b1 = __float2bfloat16(r);
    float r2 = r - __bfloat162float(b1);
    __nv_bfloat16 b2 = __float2bfloat16(r2);
    s0 = __bfloat16_as_ushort(b0);
    s1 = __bfloat16_as_ushort(b1);
    s2 = __bfloat16_as_ushort(b2);
}

__device__ __forceinline__ void split_sts(char* dst, float4 v) {
    // dst points at split-0 slot; splits are SPLIT_BYTES apart
    ushort4 o0, o1, o2;
    split3(v.x, o0.x, o1.x, o2.x);
    split3(v.y, o0.y, o1.y, o2.y);
    split3(v.z, o0.z, o1.z, o2.z);
    split3(v.w, o0.w, o1.w, o2.w);
    *reinterpret_cast<ushort4*>(dst)                   = o0;
    *reinterpret_cast<ushort4*>(dst + SPLIT_BYTES)     = o1;
    *reinterpret_cast<ushort4*>(dst + 2 * SPLIT_BYTES) = o2;
}

__device__ __forceinline__ float sig08(float x) {
    float x2 = x * x;
    // 0.8*sigmoid(x) = 0.4 + 0.8*x*p(x^2), odd Taylor to x^9 (|x| <= 1)
    float p = 2.1356922e-05f;
    p = fmaf(p, x2, -2.1081349e-04f);
    p = fmaf(p, x2,  2.0833334e-03f);
    p = fmaf(p, x2, -2.0833333e-02f);
    p = fmaf(p, x2,  0.25f);
    float s = fmaf(0.8f * x, p, 0.4f);
    if (fabsf(x) > 1.0f) s = 0.8f / (1.0f + __expf(-x));
    return s;
}

// ---------------------------------------------------------------------------
// Kernel 0: normalize prev_symbol_idx (int64 vs int32 sniff)
// ---------------------------------------------------------------------------
__global__ void prev_kernel(const void* __restrict__ p) {
    const long long* p64 = (const long long*)p;
    const int*       p32 = (const int*)p;
    bool is64 = true;
    for (int t = 0; t < 64; t++) {
        long long v = p64[t];
        if (v < 0 || v >= KCB) { is64 = false; break; }
    }
    int i = blockIdx.x * blockDim.x + threadIdx.x;
    if (i < M_TOTAL) g_prev[i] = is64 ? (int)p64[i] : p32[i];
}

// ---------------------------------------------------------------------------
// Kernel 1: cnorm[k] = ||codebook[k]||^2 (exact, f32)
// ---------------------------------------------------------------------------
__global__ void cnorm_kernel(const float* __restrict__ cb) {
    int warp = (blockIdx.x * blockDim.x + threadIdx.x) >> 5;
    int lane = threadIdx.x & 31;
    if (warp >= KCB) return;
    const float4* row = reinterpret_cast<const float4*>(cb + (size_t)warp * D2);
    float s = 0.f;
#pragma unroll
    for (int w = 0; w < 4; w++) {
        float4 v = row[lane + 32 * w];
        s += v.x * v.x + v.y * v.y + v.z * v.z + v.w * v.w;
    }
#pragma unroll
    for (int o = 16; o; o >>= 1) s += __shfl_xor_sync(0xffffffffu, s, o);
    if (lane == 0) g_cnorm[warp] = s;
}

// ---------------------------------------------------------------------------
// Kernel 2: HMMA (mma.sync bf16, 6-term exact split) GEMM + bias + argmin
// Block tile 128x128, warps 2(m) x 4(n), warp tile 64x32 (4x4 m16n8 frags).
// K staged 16 at a time, double-buffered, on-the-fly f32 -> 3x bf16 split.
// ---------------------------------------------------------------------------
__global__ __launch_bounds__(256, 2) void vq_hmma_kernel(
    const float* __restrict__ zr, const float* __restrict__ zi,
    const float* __restrict__ cb, const float* __restrict__ adj)
{
    extern __shared__ __align__(16) char smem[];
    unsigned long long* sRed = reinterpret_cast<unsigned long long*>(smem + SRED_OFF);

    const int tid    = threadIdx.x;
    const int lane   = tid & 31;
    const int wid    = tid >> 5;
    const int warp_m = wid & 1;        // 0..1  (64 rows each)
    const int warp_n = wid >> 1;       // 0..3  (32 cols each)
    const int m0     = blockIdx.x * BLK_M;

    // init argmin keys (2048 u64, 8 per thread)
#pragma unroll
    for (int i = 0; i < 8; i++) sRed[tid + 256 * i] = ~0ULL;

    // per-thread output rows (mi x {0,8}) and their prev indices
    int prev8[8];
#pragma unroll
    for (int mi = 0; mi < 4; mi++) {
#pragma unroll
        for (int h = 0; h < 2; h++)
            prev8[mi * 2 + h] = g_prev[m0 + warp_m * 64 + mi * 16 + (lane >> 2) + h * 8];
    }

    // staging assignment: thread covers row (tid>>1), 8 consecutive k at (tid&1)*8
    const int srow = tid >> 1;
    const int skc  = (tid & 1) * 8;
    const float* const arow_r = zr + (size_t)(m0 + srow) * DHALF;
    const float* const arow_i = zi + (size_t)(m0 + srow) * DHALF;

    float acc[4][4][4];
#pragma unroll
    for (int mi = 0; mi < 4; mi++)
#pragma unroll
        for (int ni = 0; ni < 4; ni++)
#pragma unroll
            for (int e = 0; e < 4; e++) acc[mi][ni][e] = 0.f;

    // ---- prologue: stage 0 (nt=0, ks=0) into buffer 0 ----
    {
        const int kd = skc;
        float4 va0 = *reinterpret_cast<const float4*>(arow_r + kd);
        float4 va1 = *reinterpret_cast<const float4*>(arow_r + kd + 4);
        const float* brow = cb + (size_t)srow * D2 + kd;
        float4 vb0 = *reinterpret_cast<const float4*>(brow);
        float4 vb1 = *reinterpret_cast<const float4*>(brow + 4);
        char* da = smem + srow * 48 + skc * 2;
        char* db = smem + 3 * SPLIT_BYTES + srow * 48 + skc * 2;
        split_sts(da, va0);     split_sts(da + 8, va1);
        split_sts(db, vb0);     split_sts(db + 8, vb1);
    }

    const int pa[6] = { 0, 0, 1, 1, 0, 2 };
    const int pb[6] = { 0, 1, 0, 1, 2, 0 };

    for (int s = 0; s < NSTAGES; s++) {
        __syncthreads();
        const bool more = (s + 1 < NSTAGES);

        // ---- LDG next stage (latency hidden by mma section) ----
        float4 va0, va1, vb0, vb1;
        if (more) {
            const int nt2 = (s + 1) >> 5;
            const int kd  = ((s + 1) & 31) * 16 + skc;
            const float* asrc = (kd < DHALF) ? (arow_r + kd) : (arow_i + kd - DHALF);
            va0 = *reinterpret_cast<const float4*>(asrc);
            va1 = *reinterpret_cast<const float4*>(asrc + 4);
            const float* bsrc = cb + (size_t)(nt2 * BLK_N + srow) * D2 + kd;
            vb0 = *reinterpret_cast<const float4*>(bsrc);
            vb1 = *reinterpret_cast<const float4*>(bsrc + 4);
        }

        // ---- compute current stage: 6 split terms x 16 mma ----
        {
            const char* buf = smem + (s & 1) * STAGE_BYTES;
            const int fo = (lane >> 2) * 48 + (lane & 3) * 4;
#pragma unroll
            for (int t = 0; t < 6; t++) {
                const char* pbs = buf + 3 * SPLIT_BYTES + pb[t] * SPLIT_BYTES
                                + (warp_n * 32) * 48 + fo;
                uint32_t bf[4][2];
#pragma unroll
                for (int ni = 0; ni < 4; ni++) {
                    bf[ni][0] = *reinterpret_cast<const uint32_t*>(pbs + ni * 8 * 48);
                    bf[ni][1] = *reinterpret_cast<const uint32_t*>(pbs + ni * 8 * 48 + 16);
                }
#pragma unroll
                for (int mi = 0; mi < 4; mi++) {
                    const char* pas = buf + pa[t] * SPLIT_BYTES
                                    + (warp_m * 64 + mi * 16) * 48 + fo;
                    uint32_t af[4];
                    af[0] = *reinterpret_cast<const uint32_t*>(pas);
                    af[1] = *reinterpret_cast<const uint32_t*>(pas + 8 * 48);
                    af[2] = *reinterpret_cast<const uint32_t*>(pas + 16);
                    af[3] = *reinterpret_cast<const uint32_t*>(pas + 8 * 48 + 16);
#pragma unroll
                    for (int ni = 0; ni < 4; ni++)
                        mma_bf16(acc[mi][ni], af, bf[ni]);
                }
            }
        }

        // ---- split + STS next stage into other buffer ----
        if (more) {
            char* nb = smem + ((s + 1) & 1) * STAGE_BYTES;
            char* da = nb + srow * 48 + skc * 2;
            char* db = nb + 3 * SPLIT_BYTES + srow * 48 + skc * 2;
            split_sts(da, va0);     split_sts(da + 8, va1);
            split_sts(db, vb0);     split_sts(db + 8, vb1);
        }

        // ---- epilogue at end of each n-tile ----
        if ((s & 31) == 31) {
            const int n0 = (s >> 5) * BLK_N;
#pragma unroll
            for (int mi = 0; mi < 4; mi++) {
#pragma unroll
                for (int h = 0; h < 2; h++) {
                    const int r = warp_m * 64 + mi * 16 + (lane >> 2) + h * 8;
                    const float* arow = adj + (size_t)prev8[mi * 2 + h] * KCB;
                    unsigned long long b = ~0ULL;
#pragma unroll
                    for (int ni = 0; ni < 4; ni++) {
                        const int n = n0 + warp_n * 32 + ni * 8 + (lane & 3) * 2;
                        float2 g  = *reinterpret_cast<const float2*>(arow + n);
                        float2 cn = *reinterpret_cast<const float2*>(g_cnorm + n);
                        float s0 = cn.x - 2.0f * acc[mi][ni][h * 2 + 0] - sig08(g.x);
                        float s1 = cn.y - 2.0f * acc[mi][ni][h * 2 + 1] - sig08(g.y);
                        unsigned u0 = __float_as_uint(s0);
                        u0 = (u0 & 0x80000000u) ? ~u0 : (u0 | 0x80000000u);
                        unsigned u1 = __float_as_uint(s1);
                        u1 = (u1 & 0x80000000u) ? ~u1 : (u1 | 0x80000000u);
                        unsigned long long c0 = ((unsigned long long)u0 << 32) | (unsigned)n;
                        unsigned long long c1 = ((unsigned long long)u1 << 32) | (unsigned)(n + 1);
                        b = (c0 < b) ? c0 : b;
                        b = (c1 < b) ? c1 : b;
                    }
                    unsigned long long* slot = &sRed[r * 16 + warp_n * 4 + (lane & 3)];
                    if (b < *slot) *slot = b;   // single-owner slot, no race
                }
            }
#pragma unroll
            for (int mi = 0; mi < 4; mi++)
#pragma unroll
                for (int ni = 0; ni < 4; ni++)
#pragma unroll
                    for (int e = 0; e < 4; e++) acc[mi][ni][e] = 0.f;
        }
    }

    __syncthreads();
    if (tid < BLK_M) {
        unsigned long long b = sRed[tid * 16];
#pragma unroll
        for (int t = 1; t < 16; t++) {
            unsigned long long c = sRed[tid * 16 + t];
            b = (c < b) ? c : b;
        }
        g_idx[m0 + tid] = (int)(b & 0xffffffffu);
    }
}

// ---------------------------------------------------------------------------
// Kernel 3: gather z_q = codebook[idx], write outputs, per-row squared error
// ---------------------------------------------------------------------------
__global__ void gather_kernel(const float* __restrict__ zr,
                              const float* __restrict__ zi,
                              const float* __restrict__ cb,
                              float* __restrict__ out)
{
    __shared__ float sw[4];
    const int row = blockIdx.x;
    const int tid = threadIdx.x;   // 128 threads, 4 floats each
    const int idx = g_idx[row];
    const int j   = tid * 4;

    float4 c = *reinterpret_cast<const float4*>(cb + (size_t)idx * D2 + j);
    float4 z;
    float* o;
    if (j < DHALF) {
        z = *reinterpret_cast<const float4*>(zr + (size_t)row * DHALF + j);
        o = out + OUT_REAL_OFF + (size_t)row * DHALF + j;
    } else {
        z = *reinterpret_cast<const float4*>(zi + (size_t)row * DHALF + (j - DHALF));
        o = out + OUT_IMAG_OFF + (size_t)row * DHALF + (j - DHALF);
    }
    *reinterpret_cast<float4*>(o) = c;

    float dx = c.x - z.x, dy = c.y - z.y, dz = c.z - z.z, dw = c.w - z.w;
    float s = dx * dx + dy * dy + dz * dz + dw * dw;
#pragma unroll
    for (int of = 16; of; of >>= 1) s += __shfl_xor_sync(0xffffffffu, s, of);
    if ((tid & 31) == 0) sw[tid >> 5] = s;
    __syncthreads();
    if (tid == 0) {
        g_rowsum[row] = sw[0] + sw[1] + sw[2] + sw[3];
        out[OUT_IDX_OFF + row] = (float)idx;
    }
}

// ---------------------------------------------------------------------------
// Kernel 4: deterministic final loss reduction
// ---------------------------------------------------------------------------
__global__ void loss_kernel(float* __restrict__ out) {
    __shared__ float sm[1024];
    const int tid = threadIdx.x;
    float s = 0.f;
#pragma unroll 1
    for (int k = 0; k < 32; k++) s += g_rowsum[tid + 1024 * k];
    sm[tid] = s;
    __syncthreads();
    for (int off = 512; off; off >>= 1) {
        if (tid < off) sm[tid] += sm[tid + off];
        __syncthreads();
    }
    if (tid == 0) out[OUT_LOSS_OFF] = sm[0] * (1.01f / 16777216.0f);
}

// ---------------------------------------------------------------------------
extern "C" void kernel_launch(void* const* d_in, const int* in_sizes, int n_in,
                              void* d_out, int out_size) {
    const float* zr   = (const float*)d_in[0];
    const float* zi   = (const float*)d_in[1];
    const void*  prev = d_in[2];
    const float* cb   = (const float*)d_in[3];
    const float* adj  = (const float*)d_in[4];
    float* out = (float*)d_out;

    cudaFuncSetAttribute(vq_hmma_kernel,
                         cudaFuncAttributeMaxDynamicSharedMemorySize, SMEM_TOTAL);

    prev_kernel<<<(M_TOTAL + 255) / 256, 256>>>(prev);
    cnorm_kernel<<<KCB / 8, 256>>>(cb);
    vq_hmma_kernel<<<M_TOTAL / BLK_M, 256, SMEM_TOTAL>>>(zr, zi, cb, adj);
    gather_kernel<<<M_TOTAL, 128>>>(zr, zi, cb, out);
    loss_kernel<<<1, 1024>>>(out);
}

// round 7
// speedup vs baseline: 2.9391x; 1.4729x over previous
#include <cuda_runtime.h>
#include <cuda_fp16.h>
#include <cstdint>

#define M_TOTAL 32768
#define DHALF   256
#define D2      512
#define KCB     4096

#define BLK_M 128
#define BLK_N 128
#define NTILES  (KCB / BLK_N)       // 32
#define KSTAGES (D2 / 16)           // 32 k16-stages per n-tile
#define NSTAGES (NTILES * KSTAGES)  // 1024

// smem: per split tile 128 rows x 48B (16 fp16 = 32B data + 16B pad)
#define SPLIT_BYTES 6144
#define STAGE_BYTES (4 * SPLIT_BYTES)            // A0,A1,B0,B1 = 24576
#define SRED_OFF    (3 * STAGE_BYTES)            // 73728 (3-deep ring)
#define SMEM_TOTAL  (SRED_OFF + BLK_M * 16 * 8)  // + 16KB keys = 90112

#define OUT_REAL_OFF 0
#define OUT_IMAG_OFF 8388608
#define OUT_LOSS_OFF 16777216
#define OUT_IDX_OFF  16777217

__device__ __align__(16) float g_cnorm[KCB];
__device__ int   g_prev[M_TOTAL];
__device__ int   g_idx[M_TOTAL];
__device__ float g_rowsum[M_TOTAL];
// 2-way fp16 splits, K-major [row][k 0..511]
__device__ __align__(16) __half g_zh[2][(size_t)M_TOTAL * D2];
__device__ __align__(16) __half g_ch[2][(size_t)KCB * D2];

// ---------------------------------------------------------------------------
__device__ __forceinline__ uint32_t smem_u32(const void* p) {
    uint32_t a;
    asm("{ .reg .u64 t; cvta.to.shared.u64 t, %1; cvt.u32.u64 %0, t; }"
        : "=r"(a) : "l"(p));
    return a;
}

__device__ __forceinline__ void cp16(uint32_t dst, const void* src) {
    asm volatile("cp.async.cg.shared.global [%0], [%1], 16;"
                 :: "r"(dst), "l"(src) : "memory");
}
#define CP_COMMIT() asm volatile("cp.async.commit_group;" ::: "memory")
#define CP_WAIT1()  asm volatile("cp.async.wait_group 1;" ::: "memory")

__device__ __forceinline__ void ldmatrix_x4(uint32_t* r, uint32_t addr) {
    asm volatile("ldmatrix.sync.aligned.m8n8.x4.shared.b16 {%0,%1,%2,%3}, [%4];"
                 : "=r"(r[0]), "=r"(r[1]), "=r"(r[2]), "=r"(r[3]) : "r"(addr));
}

__device__ __forceinline__ void mma_f16(float* d, const uint32_t* a,
                                        const uint32_t* b) {
    asm volatile(
        "mma.sync.aligned.m16n8k16.row.col.f32.f16.f16.f32 "
        "{%0,%1,%2,%3},{%4,%5,%6,%7},{%8,%9},{%0,%1,%2,%3};"
        : "+f"(d[0]), "+f"(d[1]), "+f"(d[2]), "+f"(d[3])
        : "r"(a[0]), "r"(a[1]), "r"(a[2]), "r"(a[3]), "r"(b[0]), "r"(b[1]));
}

// exact 2-way fp16 split: v = h0 + h1 (to ~2^-22 rel)
__device__ __forceinline__ void split2(float v, unsigned short& s0,
                                       unsigned short& s1) {
    __half h0 = __float2half_rn(v);
    __half h1 = __float2half_rn(v - __half2float(h0));
    s0 = __half_as_ushort(h0);
    s1 = __half_as_ushort(h1);
}

__device__ __forceinline__ float sig08(float x) {
    float x2 = x * x;
    // 0.8*sigmoid(x) = 0.4 + 0.8*x*p(x^2), odd Taylor to x^9 (|x| <= 1)
    float p = 2.1356922e-05f;
    p = fmaf(p, x2, -2.1081349e-04f);
    p = fmaf(p, x2,  2.0833334e-03f);
    p = fmaf(p, x2, -2.0833333e-02f);
    p = fmaf(p, x2,  0.25f);
    float s = fmaf(0.8f * x, p, 0.4f);
    if (fabsf(x) > 1.0f) s = 0.8f / (1.0f + __expf(-x));
    return s;
}

// ---------------------------------------------------------------------------
// Kernel 0: normalize prev_symbol_idx (int64 vs int32 sniff)
// ---------------------------------------------------------------------------
__global__ void prev_kernel(const void* __restrict__ p) {
    const long long* p64 = (const long long*)p;
    const int*       p32 = (const int*)p;
    bool is64 = true;
    for (int t = 0; t < 64; t++) {
        long long v = p64[t];
        if (v < 0 || v >= KCB) { is64 = false; break; }
    }
    int i = blockIdx.x * blockDim.x + threadIdx.x;
    if (i < M_TOTAL) g_prev[i] = is64 ? (int)p64[i] : p32[i];
}

// ---------------------------------------------------------------------------
// Kernel 1: cnorm[k] = ||codebook[k]||^2 (exact, f32)
// ---------------------------------------------------------------------------
__global__ void cnorm_kernel(const float* __restrict__ cb) {
    int warp = (blockIdx.x * blockDim.x + threadIdx.x) >> 5;
    int lane = threadIdx.x & 31;
    if (warp >= KCB) return;
    const float4* row = reinterpret_cast<const float4*>(cb + (size_t)warp * D2);
    float s = 0.f;
#pragma unroll
    for (int w = 0; w < 4; w++) {
        float4 v = row[lane + 32 * w];
        s += v.x * v.x + v.y * v.y + v.z * v.z + v.w * v.w;
    }
#pragma unroll
    for (int o = 16; o; o >>= 1) s += __shfl_xor_sync(0xffffffffu, s, o);
    if (lane == 0) g_cnorm[warp] = s;
}

// ---------------------------------------------------------------------------
// Split kernels: f32 -> 2x fp16 slices
// ---------------------------------------------------------------------------
__global__ void split_z_kernel(const float* __restrict__ zr,
                               const float* __restrict__ zi) {
    int g = blockIdx.x * blockDim.x + threadIdx.x;
    int m  = g >> 7;
    int k4 = (g & 127) * 4;
    float4 v = (k4 < DHALF)
        ? *reinterpret_cast<const float4*>(zr + (size_t)m * DHALF + k4)
        : *reinterpret_cast<const float4*>(zi + (size_t)m * DHALF + (k4 - DHALF));
    ushort4 o0, o1;
    split2(v.x, o0.x, o1.x);
    split2(v.y, o0.y, o1.y);
    split2(v.z, o0.z, o1.z);
    split2(v.w, o0.w, o1.w);
    size_t off = (size_t)m * D2 + k4;
    *reinterpret_cast<ushort4*>(&g_zh[0][off]) = o0;
    *reinterpret_cast<ushort4*>(&g_zh[1][off]) = o1;
}

__global__ void split_cb_kernel(const float* __restrict__ cb) {
    int g = blockIdx.x * blockDim.x + threadIdx.x;
    size_t off = (size_t)g * 4;
    float4 v = *reinterpret_cast<const float4*>(cb + off);
    ushort4 o0, o1;
    split2(v.x, o0.x, o1.x);
    split2(v.y, o0.y, o1.y);
    split2(v.z, o0.z, o1.z);
    split2(v.w, o0.w, o1.w);
    *reinterpret_cast<ushort4*>(&g_ch[0][off]) = o0;
    *reinterpret_cast<ushort4*>(&g_ch[1][off]) = o1;
}

// ---------------------------------------------------------------------------
// cp.async one k16-stage (4 tiles x 128 rows x 32B); 4 x 16B per thread
// ---------------------------------------------------------------------------
__device__ __forceinline__ void stage_cp(uint32_t sbase, int buf, int m0,
                                         int s, int tid) {
    const int nt = s >> 5;
    const int kb = (s & 31) * 16;
    const int row = tid >> 1, h = tid & 1;
    const uint32_t d = sbase + buf * STAGE_BYTES + row * 48 + h * 16;
    const size_t aoff = (size_t)(m0 + row) * D2 + kb + h * 8;
    const size_t boff = (size_t)(nt * BLK_N + row) * D2 + kb + h * 8;
    cp16(d,                   &g_zh[0][aoff]);
    cp16(d + SPLIT_BYTES,     &g_zh[1][aoff]);
    cp16(d + 2 * SPLIT_BYTES, &g_ch[0][boff]);
    cp16(d + 3 * SPLIT_BYTES, &g_ch[1][boff]);
}

// ---------------------------------------------------------------------------
// Kernel 2: HMMA fp16 4-term exact-split GEMM + bias + argmin
// Block 128x128, warps 2(m) x 4(n), warp tile 64x32, k16 stages,
// 3-deep cp.async ring, ldmatrix A frags, one syncthreads/stage.
// ---------------------------------------------------------------------------
__global__ __launch_bounds__(256, 2) void vq_hmma_kernel(const float* __restrict__ adj)
{
    extern __shared__ __align__(16) char smem[];
    unsigned long long* sRed = reinterpret_cast<unsigned long long*>(smem + SRED_OFF);
    const uint32_t sbase = smem_u32(smem);

    const int tid    = threadIdx.x;
    const int lane   = tid & 31;
    const int wid    = tid >> 5;
    const int warp_m = wid & 1;       // 0..1  (64 rows)
    const int warp_n = wid >> 1;      // 0..3  (32 cols)
    const int m0     = blockIdx.x * BLK_M;

#pragma unroll
    for (int i = 0; i < 8; i++) sRed[tid + 256 * i] = ~0ULL;

    int prev8[8];
#pragma unroll
    for (int mi = 0; mi < 4; mi++)
#pragma unroll
        for (int h = 0; h < 2; h++)
            prev8[mi * 2 + h] = g_prev[m0 + warp_m * 64 + mi * 16 + (lane >> 2) + h * 8];

    float acc[4][4][4];
#pragma unroll
    for (int mi = 0; mi < 4; mi++)
#pragma unroll
        for (int ni = 0; ni < 4; ni++)
#pragma unroll
            for (int e = 0; e < 4; e++) acc[mi][ni][e] = 0.f;

    // prologue: stages 0,1
    stage_cp(sbase, 0, m0, 0, tid); CP_COMMIT();
    stage_cp(sbase, 1, m0, 1, tid); CP_COMMIT();

    // fragment addressing
    const int fo    = (lane >> 2) * 48 + (lane & 3) * 4;     // B frag offset
    const int arow8 = ((lane >> 3) & 1) * 8 + (lane & 7);    // ldmatrix row-in-16
    const int akoff = (lane >> 4) * 16;                      // ldmatrix k half

    for (int s = 0; s < NSTAGES; s++) {
        CP_WAIT1();
        __syncthreads();
        if (s + 2 < NSTAGES) stage_cp(sbase, (s + 2) % 3, m0, s + 2, tid);
        CP_COMMIT();

        const uint32_t buf = sbase + (s % 3) * STAGE_BYTES;
        const char*    bufc = smem + (s % 3) * STAGE_BYTES;

        // B fragments: both splits (conflict-free LDS.32)
        uint32_t bF[2][4][2];
#pragma unroll
        for (int sp = 0; sp < 2; sp++)
#pragma unroll
            for (int ni = 0; ni < 4; ni++) {
                const char* p = bufc + (2 + sp) * SPLIT_BYTES
                              + (warp_n * 32 + ni * 8) * 48 + fo;
                bF[sp][ni][0] = *reinterpret_cast<const uint32_t*>(p);
                bF[sp][ni][1] = *reinterpret_cast<const uint32_t*>(p + 16);
            }

        // A splits sequentially (keeps regs low); 4 cross terms total
#pragma unroll
        for (int sp = 0; sp < 2; sp++) {
            uint32_t aF[4][4];
#pragma unroll
            for (int mi = 0; mi < 4; mi++)
                ldmatrix_x4(aF[mi], buf + sp * SPLIT_BYTES
                            + (warp_m * 64 + mi * 16 + arow8) * 48 + akoff);
#pragma unroll
            for (int mi = 0; mi < 4; mi++)
#pragma unroll
                for (int ni = 0; ni < 4; ni++) {
                    mma_f16(acc[mi][ni], aF[mi], bF[0][ni]);
                    mma_f16(acc[mi][ni], aF[mi], bF[1][ni]);
                }
        }

        // epilogue at end of each n-tile
        if ((s & 31) == 31) {
            const int n0 = (s >> 5) * BLK_N;
#pragma unroll
            for (int mi = 0; mi < 4; mi++) {
#pragma unroll
                for (int h = 0; h < 2; h++) {
                    const int r = warp_m * 64 + mi * 16 + (lane >> 2) + h * 8;
                    const float* arow = adj + (size_t)prev8[mi * 2 + h] * KCB;
                    unsigned long long b = ~0ULL;
#pragma unroll
                    for (int ni = 0; ni < 4; ni++) {
                        const int n = n0 + warp_n * 32 + ni * 8 + (lane & 3) * 2;
                        float2 g  = *reinterpret_cast<const float2*>(arow + n);
                        float2 cn = *reinterpret_cast<const float2*>(g_cnorm + n);
                        float s0 = cn.x - 2.0f * acc[mi][ni][h * 2 + 0] - sig08(g.x);
                        float s1 = cn.y - 2.0f * acc[mi][ni][h * 2 + 1] - sig08(g.y);
                        unsigned u0 = __float_as_uint(s0);
                        u0 = (u0 & 0x80000000u) ? ~u0 : (u0 | 0x80000000u);
                        unsigned u1 = __float_as_uint(s1);
                        u1 = (u1 & 0x80000000u) ? ~u1 : (u1 | 0x80000000u);
                        unsigned long long c0 = ((unsigned long long)u0 << 32) | (unsigned)n;
                        unsigned long long c1 = ((unsigned long long)u1 << 32) | (unsigned)(n + 1);
                        b = (c0 < b) ? c0 : b;
                        b = (c1 < b) ? c1 : b;
                    }
                    unsigned long long* slot = &sRed[r * 16 + warp_n * 4 + (lane & 3)];
                    if (b < *slot) *slot = b;   // single-owner slot
                }
            }
#pragma unroll
            for (int mi = 0; mi < 4; mi++)
#pragma unroll
                for (int ni = 0; ni < 4; ni++)
#pragma unroll
                    for (int e = 0; e < 4; e++) acc[mi][ni][e] = 0.f;
        }
    }

    __syncthreads();
    if (tid < BLK_M) {
        unsigned long long b = sRed[tid * 16];
#pragma unroll
        for (int t = 1; t < 16; t++) {
            unsigned long long c = sRed[tid * 16 + t];
            b = (c < b) ? c : b;
        }
        g_idx[m0 + tid] = (int)(b & 0xffffffffu);
    }
}

// ---------------------------------------------------------------------------
// Kernel 3: gather z_q = codebook[idx], write outputs, per-row squared error
// ---------------------------------------------------------------------------
__global__ void gather_kernel(const float* __restrict__ zr,
                              const float* __restrict__ zi,
                              const float* __restrict__ cb,
                              float* __restrict__ out)
{
    __shared__ float sw[4];
    const int row = blockIdx.x;
    const int tid = threadIdx.x;
    const int idx = g_idx[row];
    const int j   = tid * 4;

    float4 c = *reinterpret_cast<const float4*>(cb + (size_t)idx * D2 + j);
    float4 z;
    float* o;
    if (j < DHALF) {
        z = *reinterpret_cast<const float4*>(zr + (size_t)row * DHALF + j);
        o = out + OUT_REAL_OFF + (size_t)row * DHALF + j;
    } else {
        z = *reinterpret_cast<const float4*>(zi + (size_t)row * DHALF + (j - DHALF));
        o = out + OUT_IMAG_OFF + (size_t)row * DHALF + (j - DHALF);
    }
    *reinterpret_cast<float4*>(o) = c;

    float dx = c.x - z.x, dy = c.y - z.y, dz = c.z - z.z, dw = c.w - z.w;
    float s = dx * dx + dy * dy + dz * dz + dw * dw;
#pragma unroll
    for (int of = 16; of; of >>= 1) s += __shfl_xor_sync(0xffffffffu, s, of);
    if ((tid & 31) == 0) sw[tid >> 5] = s;
    __syncthreads();
    if (tid == 0) {
        g_rowsum[row] = sw[0] + sw[1] + sw[2] + sw[3];
        out[OUT_IDX_OFF + row] = (float)idx;
    }
}

// ---------------------------------------------------------------------------
// Kernel 4: deterministic final loss reduction
// ---------------------------------------------------------------------------
__global__ void loss_kernel(float* __restrict__ out) {
    __shared__ float sm[1024];
    const int tid = threadIdx.x;
    float s = 0.f;
#pragma unroll 1
    for (int k = 0; k < 32; k++) s += g_rowsum[tid + 1024 * k];
    sm[tid] = s;
    __syncthreads();
    for (int off = 512; off; off >>= 1) {
        if (tid < off) sm[tid] += sm[tid + off];
        __syncthreads();
    }
    if (tid == 0) out[OUT_LOSS_OFF] = sm[0] * (1.01f / 16777216.0f);
}

// ---------------------------------------------------------------------------
extern "C" void kernel_launch(void* const* d_in, const int* in_sizes, int n_in,
                              void* d_out, int out_size) {
    const float* zr   = (const float*)d_in[0];
    const float* zi   = (const float*)d_in[1];
    const void*  prev = d_in[2];
    const float* cb   = (const float*)d_in[3];
    const float* adj  = (const float*)d_in[4];
    float* out = (float*)d_out;

    cudaFuncSetAttribute(vq_hmma_kernel,
                         cudaFuncAttributeMaxDynamicSharedMemorySize, SMEM_TOTAL);

    prev_kernel<<<(M_TOTAL + 255) / 256, 256>>>(prev);
    cnorm_kernel<<<KCB / 8, 256>>>(cb);
    split_z_kernel<<<(M_TOTAL * D2 / 4) / 256, 256>>>(zr, zi);
    split_cb_kernel<<<(KCB * D2 / 4) / 256, 256>>>(cb);
    vq_hmma_kernel<<<M_TOTAL / BLK_M, 256, SMEM_TOTAL>>>(adj);
    gather_kernel<<<M_TOTAL, 128>>>(zr, zi, cb, out);
    loss_kernel<<<1, 1024>>>(out);
}

// round 8
// speedup vs baseline: 3.6105x; 1.2284x over previous
#include <cuda_runtime.h>
#include <cuda_fp16.h>
#include <cstdint>

#define M_TOTAL 32768
#define DHALF   256
#define D2      512
#define KCB     4096

#define BLK_M 128
#define BLK_N 128
#define NTILES  (KCB / BLK_N)       // 32
#define KSTAGES (D2 / 16)           // 32 k16-stages per n-tile
#define NSTAGES (NTILES * KSTAGES)  // 1024

// smem: per split tile 128 rows x 48B (16 fp16 = 32B data + 16B pad)
#define SPLIT_BYTES 6144
#define STAGE_BYTES (4 * SPLIT_BYTES)            // A0,A1,B0,B1 = 24576
#define SRED_OFF    (3 * STAGE_BYTES)            // 73728 (3-deep ring)
#define SMEM_TOTAL  (SRED_OFF + BLK_M * 16 * 8)  // + 16KB keys = 90112

#define OUT_REAL_OFF 0
#define OUT_IMAG_OFF 8388608
#define OUT_LOSS_OFF 16777216
#define OUT_IDX_OFF  16777217

__device__ __align__(16) float g_cnorm[KCB];
__device__ int   g_prev[M_TOTAL];
__device__ int   g_idx[M_TOTAL];
__device__ float g_rowsum[M_TOTAL];
// 2-way fp16 splits, K-major [row][k 0..511]
__device__ __align__(16) __half g_zh[2][(size_t)M_TOTAL * D2];
__device__ __align__(16) __half g_ch[2][(size_t)KCB * D2];

// ---------------------------------------------------------------------------
__device__ __forceinline__ uint32_t smem_u32(const void* p) {
    uint32_t a;
    asm("{ .reg .u64 t; cvta.to.shared.u64 t, %1; cvt.u32.u64 %0, t; }"
        : "=r"(a) : "l"(p));
    return a;
}

__device__ __forceinline__ void cp16(uint32_t dst, const void* src) {
    asm volatile("cp.async.cg.shared.global [%0], [%1], 16;"
                 :: "r"(dst), "l"(src) : "memory");
}
#define CP_COMMIT() asm volatile("cp.async.commit_group;" ::: "memory")
#define CP_WAIT1()  asm volatile("cp.async.wait_group 1;" ::: "memory")

__device__ __forceinline__ void ldmatrix_x4(uint32_t* r, uint32_t addr) {
    asm volatile("ldmatrix.sync.aligned.m8n8.x4.shared.b16 {%0,%1,%2,%3}, [%4];"
                 : "=r"(r[0]), "=r"(r[1]), "=r"(r[2]), "=r"(r[3]) : "r"(addr));
}

__device__ __forceinline__ void mma_f16(float* d, const uint32_t* a,
                                        const uint32_t* b) {
    asm volatile(
        "mma.sync.aligned.m16n8k16.row.col.f32.f16.f16.f32 "
        "{%0,%1,%2,%3},{%4,%5,%6,%7},{%8,%9},{%0,%1,%2,%3};"
        : "+f"(d[0]), "+f"(d[1]), "+f"(d[2]), "+f"(d[3])
        : "r"(a[0]), "r"(a[1]), "r"(a[2]), "r"(a[3]), "r"(b[0]), "r"(b[1]));
}

// exact 2-way fp16 split: v = h0 + h1 (to ~2^-22 rel)
__device__ __forceinline__ void split2(float v, unsigned short& s0,
                                       unsigned short& s1) {
    __half h0 = __float2half_rn(v);
    __half h1 = __float2half_rn(v - __half2float(h0));
    s0 = __half_as_ushort(h0);
    s1 = __half_as_ushort(h1);
}

__device__ __forceinline__ float sig08(float x) {
    float x2 = x * x;
    // 0.8*sigmoid(x) = 0.4 + 0.8*x*p(x^2), odd Taylor to x^9 (|x| <= 1)
    float p = 2.1356922e-05f;
    p = fmaf(p, x2, -2.1081349e-04f);
    p = fmaf(p, x2,  2.0833334e-03f);
    p = fmaf(p, x2, -2.0833333e-02f);
    p = fmaf(p, x2,  0.25f);
    float s = fmaf(0.8f * x, p, 0.4f);
    if (fabsf(x) > 1.0f) s = 0.8f / (1.0f + __expf(-x));
    return s;
}

// ---------------------------------------------------------------------------
// Kernel 0: normalize prev_symbol_idx (int64 vs int32 sniff)
// ---------------------------------------------------------------------------
__global__ void prev_kernel(const void* __restrict__ p) {
    const long long* p64 = (const long long*)p;
    const int*       p32 = (const int*)p;
    bool is64 = true;
    for (int t = 0; t < 64; t++) {
        long long v = p64[t];
        if (v < 0 || v >= KCB) { is64 = false; break; }
    }
    int i = blockIdx.x * blockDim.x + threadIdx.x;
    if (i < M_TOTAL) g_prev[i] = is64 ? (int)p64[i] : p32[i];
}

// ---------------------------------------------------------------------------
// Kernel 1: cnorm[k] = ||codebook[k]||^2 (exact, f32)
// ---------------------------------------------------------------------------
__global__ void cnorm_kernel(const float* __restrict__ cb) {
    int warp = (blockIdx.x * blockDim.x + threadIdx.x) >> 5;
    int lane = threadIdx.x & 31;
    if (warp >= KCB) return;
    const float4* row = reinterpret_cast<const float4*>(cb + (size_t)warp * D2);
    float s = 0.f;
#pragma unroll
    for (int w = 0; w < 4; w++) {
        float4 v = row[lane + 32 * w];
        s += v.x * v.x + v.y * v.y + v.z * v.z + v.w * v.w;
    }
#pragma unroll
    for (int o = 16; o; o >>= 1) s += __shfl_xor_sync(0xffffffffu, s, o);
    if (lane == 0) g_cnorm[warp] = s;
}

// ---------------------------------------------------------------------------
// Split kernels: f32 -> 2x fp16 slices
// ---------------------------------------------------------------------------
__global__ void split_z_kernel(const float* __restrict__ zr,
                               const float* __restrict__ zi) {
    int g = blockIdx.x * blockDim.x + threadIdx.x;
    int m  = g >> 7;
    int k4 = (g & 127) * 4;
    float4 v = (k4 < DHALF)
        ? *reinterpret_cast<const float4*>(zr + (size_t)m * DHALF + k4)
        : *reinterpret_cast<const float4*>(zi + (size_t)m * DHALF + (k4 - DHALF));
    ushort4 o0, o1;
    split2(v.x, o0.x, o1.x);
    split2(v.y, o0.y, o1.y);
    split2(v.z, o0.z, o1.z);
    split2(v.w, o0.w, o1.w);
    size_t off = (size_t)m * D2 + k4;
    *reinterpret_cast<ushort4*>(&g_zh[0][off]) = o0;
    *reinterpret_cast<ushort4*>(&g_zh[1][off]) = o1;
}

__global__ void split_cb_kernel(const float* __restrict__ cb) {
    int g = blockIdx.x * blockDim.x + threadIdx.x;
    size_t off = (size_t)g * 4;
    float4 v = *reinterpret_cast<const float4*>(cb + off);
    ushort4 o0, o1;
    split2(v.x, o0.x, o1.x);
    split2(v.y, o0.y, o1.y);
    split2(v.z, o0.z, o1.z);
    split2(v.w, o0.w, o1.w);
    *reinterpret_cast<ushort4*>(&g_ch[0][off]) = o0;
    *reinterpret_cast<ushort4*>(&g_ch[1][off]) = o1;
}

// ---------------------------------------------------------------------------
// cp.async one k16-stage (4 tiles x 128 rows x 32B); 4 x 16B per thread
// ---------------------------------------------------------------------------
__device__ __forceinline__ void stage_cp(uint32_t sbase, int buf, int m0,
                                         int s, int tid) {
    const int nt = s >> 5;
    const int kb = (s & 31) * 16;
    const int row = tid >> 1, h = tid & 1;
    const uint32_t d = sbase + buf * STAGE_BYTES + row * 48 + h * 16;
    const size_t aoff = (size_t)(m0 + row) * D2 + kb + h * 8;
    const size_t boff = (size_t)(nt * BLK_N + row) * D2 + kb + h * 8;
    cp16(d,                   &g_zh[0][aoff]);
    cp16(d + SPLIT_BYTES,     &g_zh[1][aoff]);
    cp16(d + 2 * SPLIT_BYTES, &g_ch[0][boff]);
    cp16(d + 3 * SPLIT_BYTES, &g_ch[1][boff]);
}

// ---------------------------------------------------------------------------
// Kernel 2: HMMA fp16 3-term exact-split GEMM + bias + argmin
// Block 128x128, warps 2(m) x 4(n), warp tile 64x32, k16 stages,
// 3-deep cp.async ring, ldmatrix for both A and B fragments.
// Terms: a0b0 + a0b1 + a1b0 (a1b1 dropped: <= 2^-22 rel, << argmin gap)
// ---------------------------------------------------------------------------
__global__ __launch_bounds__(256, 2) void vq_hmma_kernel(const float* __restrict__ adj)
{
    extern __shared__ __align__(16) char smem[];
    unsigned long long* sRed = reinterpret_cast<unsigned long long*>(smem + SRED_OFF);
    const uint32_t sbase = smem_u32(smem);

    const int tid    = threadIdx.x;
    const int lane   = tid & 31;
    const int wid    = tid >> 5;
    const int warp_m = wid & 1;       // 0..1  (64 rows)
    const int warp_n = wid >> 1;      // 0..3  (32 cols)
    const int m0     = blockIdx.x * BLK_M;

#pragma unroll
    for (int i = 0; i < 8; i++) sRed[tid + 256 * i] = ~0ULL;

    int prev8[8];
#pragma unroll
    for (int mi = 0; mi < 4; mi++)
#pragma unroll
        for (int h = 0; h < 2; h++)
            prev8[mi * 2 + h] = g_prev[m0 + warp_m * 64 + mi * 16 + (lane >> 2) + h * 8];

    float acc[4][4][4];
#pragma unroll
    for (int mi = 0; mi < 4; mi++)
#pragma unroll
        for (int ni = 0; ni < 4; ni++)
#pragma unroll
            for (int e = 0; e < 4; e++) acc[mi][ni][e] = 0.f;

    // prologue: stages 0,1
    stage_cp(sbase, 0, m0, 0, tid); CP_COMMIT();
    stage_cp(sbase, 1, m0, 1, tid); CP_COMMIT();

    // fragment addressing
    const int arow8 = ((lane >> 3) & 1) * 8 + (lane & 7);    // A ldmatrix row-in-16
    const int akoff = (lane >> 4) * 16;                      // A ldmatrix k half
    // B ldmatrix.x4: matrix q = lane>>3 -> (ni offset q>>1, k-half q&1)
    const int bq = lane >> 3, br = lane & 7;
    const int boffs = (bq >> 1) * 8 * 48 + br * 48 + (bq & 1) * 16;

    for (int s = 0; s < NSTAGES; s++) {
        CP_WAIT1();
        __syncthreads();
        if (s + 2 < NSTAGES) stage_cp(sbase, (s + 2) % 3, m0, s + 2, tid);
        CP_COMMIT();

        const uint32_t buf = sbase + (s % 3) * STAGE_BYTES;

        // B fragments via ldmatrix.x4: [split][ni][2]
        uint32_t bF[2][4][2];
#pragma unroll
        for (int sp = 0; sp < 2; sp++) {
            const uint32_t bb = buf + (2 + sp) * SPLIT_BYTES + (warp_n * 32) * 48 + boffs;
            uint32_t r0[4], r1[4];
            ldmatrix_x4(r0, bb);          // ni 0,1
            ldmatrix_x4(r1, bb + 16 * 48); // ni 2,3
            bF[sp][0][0] = r0[0]; bF[sp][0][1] = r0[1];
            bF[sp][1][0] = r0[2]; bF[sp][1][1] = r0[3];
            bF[sp][2][0] = r1[0]; bF[sp][2][1] = r1[1];
            bF[sp][3][0] = r1[2]; bF[sp][3][1] = r1[3];
        }

        // A split 0: terms a0b0 + a0b1
        {
            uint32_t aF[4][4];
#pragma unroll
            for (int mi = 0; mi < 4; mi++)
                ldmatrix_x4(aF[mi], buf + (warp_m * 64 + mi * 16 + arow8) * 48 + akoff);
#pragma unroll
            for (int mi = 0; mi < 4; mi++)
#pragma unroll
                for (int ni = 0; ni < 4; ni++) {
                    mma_f16(acc[mi][ni], aF[mi], bF[0][ni]);
                    mma_f16(acc[mi][ni], aF[mi], bF[1][ni]);
                }
        }
        // A split 1: term a1b0 only
        {
            uint32_t aF[4][4];
#pragma unroll
            for (int mi = 0; mi < 4; mi++)
                ldmatrix_x4(aF[mi], buf + SPLIT_BYTES
                            + (warp_m * 64 + mi * 16 + arow8) * 48 + akoff);
#pragma unroll
            for (int mi = 0; mi < 4; mi++)
#pragma unroll
                for (int ni = 0; ni < 4; ni++)
                    mma_f16(acc[mi][ni], aF[mi], bF[0][ni]);
        }

        // epilogue at end of each n-tile
        if ((s & 31) == 31) {
            const int n0 = (s >> 5) * BLK_N;
#pragma unroll
            for (int mi = 0; mi < 4; mi++) {
#pragma unroll
                for (int h = 0; h < 2; h++) {
                    const int r = warp_m * 64 + mi * 16 + (lane >> 2) + h * 8;
                    const float* arow = adj + (size_t)prev8[mi * 2 + h] * KCB;
                    unsigned long long b = ~0ULL;
#pragma unroll
                    for (int ni = 0; ni < 4; ni++) {
                        const int n = n0 + warp_n * 32 + ni * 8 + (lane & 3) * 2;
                        float2 g  = *reinterpret_cast<const float2*>(arow + n);
                        float2 cn = *reinterpret_cast<const float2*>(g_cnorm + n);
                        float s0 = cn.x - 2.0f * acc[mi][ni][h * 2 + 0] - sig08(g.x);
                        float s1 = cn.y - 2.0f * acc[mi][ni][h * 2 + 1] - sig08(g.y);
                        unsigned u0 = __float_as_uint(s0);
                        u0 = (u0 & 0x80000000u) ? ~u0 : (u0 | 0x80000000u);
                        unsigned u1 = __float_as_uint(s1);
                        u1 = (u1 & 0x80000000u) ? ~u1 : (u1 | 0x80000000u);
                        unsigned long long c0 = ((unsigned long long)u0 << 32) | (unsigned)n;
                        unsigned long long c1 = ((unsigned long long)u1 << 32) | (unsigned)(n + 1);
                        b = (c0 < b) ? c0 : b;
                        b = (c1 < b) ? c1 : b;
                    }
                    unsigned long long* slot = &sRed[r * 16 + warp_n * 4 + (lane & 3)];
                    if (b < *slot) *slot = b;   // single-owner slot
                }
            }
#pragma unroll
            for (int mi = 0; mi < 4; mi++)
#pragma unroll
                for (int ni = 0; ni < 4; ni++)
#pragma unroll
                    for (int e = 0; e < 4; e++) acc[mi][ni][e] = 0.f;
        }
    }

    __syncthreads();
    if (tid < BLK_M) {
        unsigned long long b = sRed[tid * 16];
#pragma unroll
        for (int t = 1; t < 16; t++) {
            unsigned long long c = sRed[tid * 16 + t];
            b = (c < b) ? c : b;
        }
        g_idx[m0 + tid] = (int)(b & 0xffffffffu);
    }
}

// ---------------------------------------------------------------------------
// Kernel 3: gather z_q = codebook[idx], write outputs, per-row squared error
// ---------------------------------------------------------------------------
__global__ void gather_kernel(const float* __restrict__ zr,
                              const float* __restrict__ zi,
                              const float* __restrict__ cb,
                              float* __restrict__ out)
{
    __shared__ float sw[4];
    const int row = blockIdx.x;
    const int tid = threadIdx.x;
    const int idx = g_idx[row];
    const int j   = tid * 4;

    float4 c = *reinterpret_cast<const float4*>(cb + (size_t)idx * D2 + j);
    float4 z;
    float* o;
    if (j < DHALF) {
        z = *reinterpret_cast<const float4*>(zr + (size_t)row * DHALF + j);
        o = out + OUT_REAL_OFF + (size_t)row * DHALF + j;
    } else {
        z = *reinterpret_cast<const float4*>(zi + (size_t)row * DHALF + (j - DHALF));
        o = out + OUT_IMAG_OFF + (size_t)row * DHALF + (j - DHALF);
    }
    *reinterpret_cast<float4*>(o) = c;

    float dx = c.x - z.x, dy = c.y - z.y, dz = c.z - z.z, dw = c.w - z.w;
    float s = dx * dx + dy * dy + dz * dz + dw * dw;
#pragma unroll
    for (int of = 16; of; of >>= 1) s += __shfl_xor_sync(0xffffffffu, s, of);
    if ((tid & 31) == 0) sw[tid >> 5] = s;
    __syncthreads();
    if (tid == 0) {
        g_rowsum[row] = sw[0] + sw[1] + sw[2] + sw[3];
        out[OUT_IDX_OFF + row] = (float)idx;
    }
}

// ---------------------------------------------------------------------------
// Kernel 4: deterministic final loss reduction
// ---------------------------------------------------------------------------
__global__ void loss_kernel(float* __restrict__ out) {
    __shared__ float sm[1024];
    const int tid = threadIdx.x;
    float s = 0.f;
#pragma unroll 1
    for (int k = 0; k < 32; k++) s += g_rowsum[tid + 1024 * k];
    sm[tid] = s;
    __syncthreads();
    for (int off = 512; off; off >>= 1) {
        if (tid < off) sm[tid] += sm[tid + off];
        __syncthreads();
    }
    if (tid == 0) out[OUT_LOSS_OFF] = sm[0] * (1.01f / 16777216.0f);
}

// ---------------------------------------------------------------------------
extern "C" void kernel_launch(void* const* d_in, const int* in_sizes, int n_in,
                              void* d_out, int out_size) {
    const float* zr   = (const float*)d_in[0];
    const float* zi   = (const float*)d_in[1];
    const void*  prev = d_in[2];
    const float* cb   = (const float*)d_in[3];
    const float* adj  = (const float*)d_in[4];
    float* out = (float*)d_out;

    cudaFuncSetAttribute(vq_hmma_kernel,
                         cudaFuncAttributeMaxDynamicSharedMemorySize, SMEM_TOTAL);

    prev_kernel<<<(M_TOTAL + 255) / 256, 256>>>(prev);
    cnorm_kernel<<<KCB / 8, 256>>>(cb);
    split_z_kernel<<<(M_TOTAL * D2 / 4) / 256, 256>>>(zr, zi);
    split_cb_kernel<<<(KCB * D2 / 4) / 256, 256>>>(cb);
    vq_hmma_kernel<<<M_TOTAL / BLK_M, 256, SMEM_TOTAL>>>(adj);
    gather_kernel<<<M_TOTAL, 128>>>(zr, zi, cb, out);
    loss_kernel<<<1, 1024>>>(out);
}